// round 3
// baseline (speedup 1.0000x reference)
#include <cuda_runtime.h>
#include <cstdint>

// BoundarySeg: out[b,j,0:768]   = sum_{d=0..5} w[b,j,d] * hidden[b, min(j+d,L-1), :]
//              out[b,j,768:1536]= hidden[b,j,:] * sum_d w[b,j,d]
// w[b,j,d] = span_adjacency[b, j, j+d] if j+d < L else 0.
// B=16, L=1024, H=768. fp32.
//
// Round-3 strategy: CTA = 8 consecutive j's. Hidden rows read directly from
// L2 via a 6-deep sliding register window (LDG.128). Results written to a
// 48KB smem tile via STS.128 (issue-only), then drained with ONE
// cp.async.bulk smem->global store per CTA (contiguous 48KB). This removes
// ~196k warp STG.128s (12cyc issue each) from the SM pipeline.

#define BB 16
#define LL 1024
#define HH 768
#define HV (HH / 4)            // 192 float4 per row
#define TJ 8                   // j's per CTA
#define SPAN 6
#define OUT_TILE_BYTES (TJ * 2 * HH * 4)   // 49152

__device__ __forceinline__ uint32_t smem_u32(const void* p) {
    uint32_t a;
    asm("{ .reg .u64 t; cvta.to.shared.u64 t, %1; cvt.u32.u64 %0, t; }"
        : "=r"(a) : "l"(p));
    return a;
}

__global__ __launch_bounds__(HV)
void boundary_seg_kernel(const float* __restrict__ adj,
                         const float* __restrict__ hid,
                         float* __restrict__ out)
{
    extern __shared__ __align__(16) char smem_raw[];
    float4* sout = reinterpret_cast<float4*>(smem_raw);        // TJ * 2*HV float4
    float*  wsm  = reinterpret_cast<float*>(smem_raw + OUT_TILE_BYTES); // TJ*SPAN

    const int tile = blockIdx.x;           // b * 128 + jt
    const int b  = tile >> 7;
    const int j0 = (tile & 127) * TJ;
    const int t  = threadIdx.x;            // float4 column of H

    const float4* __restrict__ hid4 =
        reinterpret_cast<const float4*>(hid) + (size_t)b * LL * HV;

    // Weights: 48 scalar loads done by the first 48 threads.
    if (t < TJ * SPAN) {
        const int jj = t / SPAN;
        const int d  = t - jj * SPAN;
        const int col = j0 + jj + d;
        float w = 0.0f;
        if (col < LL)
            w = __ldg(adj + ((size_t)b * LL + (j0 + jj)) * LL + col);
        wsm[jj * SPAN + d] = w;
    }

    // Sliding register window of 6 hidden rows (this thread's float4 column).
    float4 v[SPAN];
#pragma unroll
    for (int d = 0; d < SPAN; d++) {
        int r = j0 + d; if (r > LL - 1) r = LL - 1;
        v[d] = hid4[(size_t)r * HV + t];
    }

    __syncthreads();   // weights visible

#pragma unroll
    for (int jj = 0; jj < TJ; jj++) {
        const float w0 = wsm[jj * SPAN + 0], w1 = wsm[jj * SPAN + 1];
        const float w2 = wsm[jj * SPAN + 2], w3 = wsm[jj * SPAN + 3];
        const float w4 = wsm[jj * SPAN + 4], w5 = wsm[jj * SPAN + 5];
        const float wsum = ((w0 + w1) + (w2 + w3)) + (w4 + w5);

        // Prefetch the next window row before the FMA chain.
        int rn = j0 + jj + SPAN; if (rn > LL - 1) rn = LL - 1;
        const float4 vnext = hid4[(size_t)rn * HV + t];

        float4 f;
        f.x = w0 * v[0].x; f.y = w0 * v[0].y;
        f.z = w0 * v[0].z; f.w = w0 * v[0].w;
        f.x = fmaf(w1, v[1].x, f.x); f.y = fmaf(w1, v[1].y, f.y);
        f.z = fmaf(w1, v[1].z, f.z); f.w = fmaf(w1, v[1].w, f.w);
        f.x = fmaf(w2, v[2].x, f.x); f.y = fmaf(w2, v[2].y, f.y);
        f.z = fmaf(w2, v[2].z, f.z); f.w = fmaf(w2, v[2].w, f.w);
        f.x = fmaf(w3, v[3].x, f.x); f.y = fmaf(w3, v[3].y, f.y);
        f.z = fmaf(w3, v[3].z, f.z); f.w = fmaf(w3, v[3].w, f.w);
        f.x = fmaf(w4, v[4].x, f.x); f.y = fmaf(w4, v[4].y, f.y);
        f.z = fmaf(w4, v[4].z, f.z); f.w = fmaf(w4, v[4].w, f.w);
        f.x = fmaf(w5, v[5].x, f.x); f.y = fmaf(w5, v[5].y, f.y);
        f.z = fmaf(w5, v[5].z, f.z); f.w = fmaf(w5, v[5].w, f.w);

        float4 s;
        s.x = v[0].x * wsum; s.y = v[0].y * wsum;
        s.z = v[0].z * wsum; s.w = v[0].w * wsum;

        sout[jj * (2 * HV) + t]      = f;
        sout[jj * (2 * HV) + HV + t] = s;

        // Slide the window.
#pragma unroll
        for (int d = 0; d < SPAN - 1; d++) v[d] = v[d + 1];
        v[SPAN - 1] = vnext;
    }

    __syncthreads();

    // Single bulk DMA of the contiguous 48KB output tile.
    if (t == 0) {
        asm volatile("fence.proxy.async.shared::cta;" ::: "memory");
        float* dst = out + ((size_t)b * LL + j0) * (size_t)(2 * HH);
        const uint32_t s_src = smem_u32(sout);
        asm volatile(
            "cp.async.bulk.global.shared::cta.bulk_group [%0], [%1], %2;"
            :: "l"(dst), "r"(s_src), "n"(OUT_TILE_BYTES) : "memory");
        asm volatile("cp.async.bulk.commit_group;" ::: "memory");
        // Only need smem reads done before smem is reused by the next CTA.
        asm volatile("cp.async.bulk.wait_group.read 0;" ::: "memory");
    }
}

extern "C" void kernel_launch(void* const* d_in, const int* in_sizes, int n_in,
                              void* d_out, int out_size)
{
    const float* adj = (const float*)d_in[0];   // (B,L,L,1)
    const float* hid = (const float*)d_in[1];   // (B,L,H)
    float* out = (float*)d_out;                 // (B,L,2H)

    const int smem_bytes = OUT_TILE_BYTES + TJ * SPAN * (int)sizeof(float);
    static bool attr_set = false;
    if (!attr_set) {
        cudaFuncSetAttribute(boundary_seg_kernel,
                             cudaFuncAttributeMaxDynamicSharedMemorySize,
                             smem_bytes);
        attr_set = true;
    }

    const int grid = BB * (LL / TJ);            // 2048 CTAs
    boundary_seg_kernel<<<grid, HV, smem_bytes>>>(adj, hid, out);
}

// round 4
// speedup vs baseline: 1.1470x; 1.1470x over previous
#include <cuda_runtime.h>
#include <cstdint>

// BoundarySeg: out[b,j,0:768]   = sum_{d=0..5} w[b,j,d] * hidden[b, min(j+d,L-1), :]
//              out[b,j,768:1536]= hidden[b,j,:] * sum_d w[b,j,d]
// w[b,j,d] = span_adjacency[b, j, j+d] if j+d < L else 0.
// B=16, L=1024, H=768. fp32.
//
// R4: TMA bulk-copy IN (13 hidden rows -> smem, kills read latency) and
// TMA bulk-copy OUT (double-buffered 6KB per-j staging, kills STG L1tex
// pressure). SM issues only FFMA + STS + LDS; all gmem traffic is DMA.

#define BB 16
#define LL 1024
#define HH 768
#define HV (HH / 4)            // 192 float4 per row
#define TJ 8                   // j's per CTA
#define SPAN 6
#define NROWS (TJ + SPAN - 1)  // 13 rows staged
#define IN_BYTES  (NROWS * HH * 4)        // 39936
#define OUTJ_BYTES (2 * HH * 4)           // 6144 per j

struct __align__(16) SmemLayout {
    float4   in[NROWS * HV];              // 39936 B
    float4   ob[2][2 * HV];               // 2 x 6144 B
    float    w[TJ * SPAN];                // 192 B
    uint64_t mbar;
};

__device__ __forceinline__ uint32_t smem_u32(const void* p) {
    uint32_t a;
    asm("{ .reg .u64 t; cvta.to.shared.u64 t, %1; cvt.u32.u64 %0, t; }"
        : "=r"(a) : "l"(p));
    return a;
}

__global__ __launch_bounds__(HV)
void boundary_seg_kernel(const float* __restrict__ adj,
                         const float* __restrict__ hid,
                         float* __restrict__ out)
{
    extern __shared__ __align__(16) char smem_raw[];
    SmemLayout* sm = reinterpret_cast<SmemLayout*>(smem_raw);

    const int tile = blockIdx.x;           // b * 128 + jt
    const int b  = tile >> 7;
    const int j0 = (tile & 127) * TJ;
    const int t  = threadIdx.x;            // float4 column of H

    const int rl = min(NROWS, LL - j0);    // rows actually available
    const uint32_t in_bytes = (uint32_t)rl * HH * 4u;

    const uint32_t s_in   = smem_u32(sm->in);
    const uint32_t s_mbar = smem_u32(&sm->mbar);

    if (t == 0) {
        asm volatile("mbarrier.init.shared::cta.b64 [%0], %1;"
                     :: "r"(s_mbar), "r"(1) : "memory");
    }
    __syncthreads();

    if (t == 0) {
        asm volatile("mbarrier.arrive.expect_tx.shared::cta.b64 _, [%0], %1;"
                     :: "r"(s_mbar), "r"(in_bytes) : "memory");
        const float* src = hid + ((size_t)b * LL + j0) * HH;
        asm volatile(
            "cp.async.bulk.shared::cluster.global.mbarrier::complete_tx::bytes "
            "[%0], [%1], %2, [%3];"
            :: "r"(s_in), "l"(src), "r"(in_bytes), "r"(s_mbar) : "memory");
    }

    // Weights: 48 scattered loads, overlapped with the TMA.
    if (t < TJ * SPAN) {
        const int jj = t / SPAN;
        const int d  = t - jj * SPAN;
        const int col = j0 + jj + d;
        float w = 0.0f;
        if (col < LL)
            w = __ldg(adj + ((size_t)b * LL + (j0 + jj)) * LL + col);
        sm->w[jj * SPAN + d] = w;
    }
    __syncthreads();

    // Wait for the TMA bulk copy.
    {
        uint32_t done;
        do {
            asm volatile(
                "{ .reg .pred p;\n\t"
                "  mbarrier.try_wait.parity.shared::cta.b64 p, [%1], %2;\n\t"
                "  selp.b32 %0, 1, 0, p; }"
                : "=r"(done) : "r"(s_mbar), "r"(0u) : "memory");
        } while (!done);
    }

    const int rmax = rl - 1;

    // Sliding register window of 6 rows (this thread's float4 column).
    float4 v[SPAN];
#pragma unroll
    for (int d = 0; d < SPAN; d++)
        v[d] = sm->in[min(d, rmax) * HV + t];

#pragma unroll
    for (int jj = 0; jj < TJ; jj++) {
        const int buf = jj & 1;
        const float w0 = sm->w[jj * SPAN + 0], w1 = sm->w[jj * SPAN + 1];
        const float w2 = sm->w[jj * SPAN + 2], w3 = sm->w[jj * SPAN + 3];
        const float w4 = sm->w[jj * SPAN + 4], w5 = sm->w[jj * SPAN + 5];
        const float wsum = ((w0 + w1) + (w2 + w3)) + (w4 + w5);

        float4 f;
        f.x = w0 * v[0].x; f.y = w0 * v[0].y;
        f.z = w0 * v[0].z; f.w = w0 * v[0].w;
        f.x = fmaf(w1, v[1].x, f.x); f.y = fmaf(w1, v[1].y, f.y);
        f.z = fmaf(w1, v[1].z, f.z); f.w = fmaf(w1, v[1].w, f.w);
        f.x = fmaf(w2, v[2].x, f.x); f.y = fmaf(w2, v[2].y, f.y);
        f.z = fmaf(w2, v[2].z, f.z); f.w = fmaf(w2, v[2].w, f.w);
        f.x = fmaf(w3, v[3].x, f.x); f.y = fmaf(w3, v[3].y, f.y);
        f.z = fmaf(w3, v[3].z, f.z); f.w = fmaf(w3, v[3].w, f.w);
        f.x = fmaf(w4, v[4].x, f.x); f.y = fmaf(w4, v[4].y, f.y);
        f.z = fmaf(w4, v[4].z, f.z); f.w = fmaf(w4, v[4].w, f.w);
        f.x = fmaf(w5, v[5].x, f.x); f.y = fmaf(w5, v[5].y, f.y);
        f.z = fmaf(w5, v[5].z, f.z); f.w = fmaf(w5, v[5].w, f.w);

        float4 s;
        s.x = v[0].x * wsum; s.y = v[0].y * wsum;
        s.z = v[0].z * wsum; s.w = v[0].w * wsum;

        // Ensure the bulk store issued 2 iterations ago has finished
        // READING this buffer before we overwrite it.
        if (jj >= 2) {
            if (t == 0)
                asm volatile("cp.async.bulk.wait_group.read 1;" ::: "memory");
            __syncthreads();
        }

        sm->ob[buf][t]      = f;
        sm->ob[buf][HV + t] = s;

        __syncthreads();   // staging buffer filled

        if (t == 0) {
            asm volatile("fence.proxy.async.shared::cta;" ::: "memory");
            float* dst = out + ((size_t)b * LL + (j0 + jj)) * (size_t)(2 * HH);
            const uint32_t s_src = smem_u32(sm->ob[buf]);
            asm volatile(
                "cp.async.bulk.global.shared::cta.bulk_group [%0], [%1], %2;"
                :: "l"(dst), "r"(s_src), "n"(OUTJ_BYTES) : "memory");
            asm volatile("cp.async.bulk.commit_group;" ::: "memory");
        }

        // Slide the window.
#pragma unroll
        for (int d = 0; d < SPAN - 1; d++) v[d] = v[d + 1];
        v[SPAN - 1] = sm->in[min(jj + SPAN, rmax) * HV + t];
    }

    // Drain all outstanding bulk stores (smem reads) before CTA teardown.
    if (t == 0)
        asm volatile("cp.async.bulk.wait_group.read 0;" ::: "memory");
}

extern "C" void kernel_launch(void* const* d_in, const int* in_sizes, int n_in,
                              void* d_out, int out_size)
{
    const float* adj = (const float*)d_in[0];   // (B,L,L,1)
    const float* hid = (const float*)d_in[1];   // (B,L,H)
    float* out = (float*)d_out;                 // (B,L,2H)

    const int smem_bytes = (int)sizeof(SmemLayout);
    static bool attr_set = false;
    if (!attr_set) {
        cudaFuncSetAttribute(boundary_seg_kernel,
                             cudaFuncAttributeMaxDynamicSharedMemorySize,
                             smem_bytes);
        attr_set = true;
    }

    const int grid = BB * (LL / TJ);            // 2048 CTAs
    boundary_seg_kernel<<<grid, HV, smem_bytes>>>(adj, hid, out);
}

// round 5
// speedup vs baseline: 1.2161x; 1.0602x over previous
#include <cuda_runtime.h>
#include <cstdint>

// BoundarySeg: out[b,j,0:768]   = sum_{d=0..5} w[b,j,d] * hidden[b, min(j+d,L-1), :]
//              out[b,j,768:1536]= hidden[b,j,:] * sum_d w[b,j,d]
// w[b,j,d] = span_adjacency[b, j, j+d] if j+d < L else 0.
// B=16, L=1024, H=768. fp32.
//
// R5: R2 skeleton (TMA bulk-copy in + direct STG out) with TJ=4 to double
// CTA-level concurrency (27.6KB smem -> ~6-7 CTAs/SM, 4096 CTAs), and
// streaming stores (.cs) so the 96MB output stream doesn't evict the
// L2-resident hidden tensor.

#define BB 16
#define LL 1024
#define HH 768
#define HV (HH / 4)            // 192 float4 per row
#define TJ 4                   // j's per CTA
#define SPAN 6
#define NROWS (TJ + SPAN - 1)  // 9 rows staged

__device__ __forceinline__ uint32_t smem_u32(const void* p) {
    uint32_t a;
    asm("{ .reg .u64 t; cvta.to.shared.u64 t, %1; cvt.u32.u64 %0, t; }"
        : "=r"(a) : "l"(p));
    return a;
}

__device__ __forceinline__ void stcs4(float4* p, float4 v) {
    asm volatile("st.global.cs.v4.f32 [%0], {%1,%2,%3,%4};"
                 :: "l"(p), "f"(v.x), "f"(v.y), "f"(v.z), "f"(v.w) : "memory");
}

struct __align__(16) SmemLayout {
    float4   in[NROWS * HV];     // 27648 B
    float    w[TJ * SPAN];       // 96 B
    uint64_t mbar;
};

__global__ __launch_bounds__(HV)
void boundary_seg_kernel(const float* __restrict__ adj,
                         const float* __restrict__ hid,
                         float* __restrict__ out)
{
    extern __shared__ __align__(16) char smem_raw[];
    SmemLayout* sm = reinterpret_cast<SmemLayout*>(smem_raw);

    const int tile = blockIdx.x;           // b * 256 + jt
    const int b  = tile >> 8;
    const int j0 = (tile & 255) * TJ;
    const int t  = threadIdx.x;            // float4 column of H

    const int rl = min(NROWS, LL - j0);    // rows actually available
    const uint32_t in_bytes = (uint32_t)rl * HH * 4u;

    const uint32_t s_in   = smem_u32(sm->in);
    const uint32_t s_mbar = smem_u32(&sm->mbar);

    if (t == 0) {
        asm volatile("mbarrier.init.shared::cta.b64 [%0], %1;"
                     :: "r"(s_mbar), "r"(1) : "memory");
    }
    __syncthreads();

    if (t == 0) {
        asm volatile("mbarrier.arrive.expect_tx.shared::cta.b64 _, [%0], %1;"
                     :: "r"(s_mbar), "r"(in_bytes) : "memory");
        const float* src = hid + ((size_t)b * LL + j0) * HH;
        asm volatile(
            "cp.async.bulk.shared::cluster.global.mbarrier::complete_tx::bytes "
            "[%0], [%1], %2, [%3];"
            :: "r"(s_in), "l"(src), "r"(in_bytes), "r"(s_mbar) : "memory");
    }

    // Weights: 24 scattered L2 loads, overlapped with the TMA.
    if (t < TJ * SPAN) {
        const int jj = t / SPAN;
        const int d  = t - jj * SPAN;
        const int col = j0 + jj + d;
        float w = 0.0f;
        if (col < LL)
            w = __ldg(adj + ((size_t)b * LL + (j0 + jj)) * LL + col);
        sm->w[jj * SPAN + d] = w;
    }
    __syncthreads();

    // Wait for the TMA bulk copy.
    {
        uint32_t done;
        do {
            asm volatile(
                "{ .reg .pred p;\n\t"
                "  mbarrier.try_wait.parity.shared::cta.b64 p, [%1], %2;\n\t"
                "  selp.b32 %0, 1, 0, p; }"
                : "=r"(done) : "r"(s_mbar), "r"(0u) : "memory");
        } while (!done);
    }

    const int rmax = rl - 1;

    // Sliding register window of 6 rows (this thread's float4 column).
    float4 v[SPAN];
#pragma unroll
    for (int d = 0; d < SPAN; d++)
        v[d] = sm->in[min(d, rmax) * HV + t];

    float4* __restrict__ out4 = reinterpret_cast<float4*>(out);

#pragma unroll
    for (int jj = 0; jj < TJ; jj++) {
        const float w0 = sm->w[jj * SPAN + 0], w1 = sm->w[jj * SPAN + 1];
        const float w2 = sm->w[jj * SPAN + 2], w3 = sm->w[jj * SPAN + 3];
        const float w4 = sm->w[jj * SPAN + 4], w5 = sm->w[jj * SPAN + 5];
        const float wsum = ((w0 + w1) + (w2 + w3)) + (w4 + w5);

        float4 f;
        f.x = w0 * v[0].x; f.y = w0 * v[0].y;
        f.z = w0 * v[0].z; f.w = w0 * v[0].w;
        f.x = fmaf(w1, v[1].x, f.x); f.y = fmaf(w1, v[1].y, f.y);
        f.z = fmaf(w1, v[1].z, f.z); f.w = fmaf(w1, v[1].w, f.w);
        f.x = fmaf(w2, v[2].x, f.x); f.y = fmaf(w2, v[2].y, f.y);
        f.z = fmaf(w2, v[2].z, f.z); f.w = fmaf(w2, v[2].w, f.w);
        f.x = fmaf(w3, v[3].x, f.x); f.y = fmaf(w3, v[3].y, f.y);
        f.z = fmaf(w3, v[3].z, f.z); f.w = fmaf(w3, v[3].w, f.w);
        f.x = fmaf(w4, v[4].x, f.x); f.y = fmaf(w4, v[4].y, f.y);
        f.z = fmaf(w4, v[4].z, f.z); f.w = fmaf(w4, v[4].w, f.w);
        f.x = fmaf(w5, v[5].x, f.x); f.y = fmaf(w5, v[5].y, f.y);
        f.z = fmaf(w5, v[5].z, f.z); f.w = fmaf(w5, v[5].w, f.w);

        float4 s;
        s.x = v[0].x * wsum; s.y = v[0].y * wsum;
        s.z = v[0].z * wsum; s.w = v[0].w * wsum;

        const size_t obase = ((size_t)b * LL + (j0 + jj)) * (size_t)(2 * HV);
        stcs4(out4 + obase + t, f);
        stcs4(out4 + obase + HV + t, s);

        // Slide the window.
#pragma unroll
        for (int d = 0; d < SPAN - 1; d++) v[d] = v[d + 1];
        v[SPAN - 1] = sm->in[min(jj + SPAN, rmax) * HV + t];
    }
}

extern "C" void kernel_launch(void* const* d_in, const int* in_sizes, int n_in,
                              void* d_out, int out_size)
{
    const float* adj = (const float*)d_in[0];   // (B,L,L,1)
    const float* hid = (const float*)d_in[1];   // (B,L,H)
    float* out = (float*)d_out;                 // (B,L,2H)

    const int smem_bytes = (int)sizeof(SmemLayout);
    static bool attr_set = false;
    if (!attr_set) {
        cudaFuncSetAttribute(boundary_seg_kernel,
                             cudaFuncAttributeMaxDynamicSharedMemorySize,
                             smem_bytes);
        attr_set = true;
    }

    const int grid = BB * (LL / TJ);            // 4096 CTAs
    boundary_seg_kernel<<<grid, HV, smem_bytes>>>(adj, hid, out);
}